// round 8
// baseline (speedup 1.0000x reference)
#include <cuda_runtime.h>
#include <cuda_bf16.h>
#include <cstdint>

#define BATCH 32
#define NA 8400
#define NJ 100
#define NC 80
#define KTOP 13
#define EPSV 1e-9f
#define CAND_CAP 512
#define NCLAIM (NJ * KTOP)        // 1300 claims per batch image

// ---------------- device scratch (all fully overwritten each call; no init) ----
__device__ int          g_topa [BATCH * NJ * KTOP];   // -1 = unused slot
__device__ float        g_topal[BATCH * NJ * KTOP];
__device__ float        g_topio[BATCH * NJ * KTOP];
__device__ float        g_alsel[BATCH * NA];          // read only where claimed
__device__ unsigned int g_rec  [BATCH * NA];          // (lab<<16)|(g<<8)|pos
__device__ float        g_norm [BATCH * NA];

__device__ __forceinline__ float iou_box(float gx1, float gy1, float gx2, float gy2,
                                         float4 p, float garea) {
    float ix1 = fmaxf(gx1, p.x), iy1 = fmaxf(gy1, p.y);
    float ix2 = fminf(gx2, p.z), iy2 = fminf(gy2, p.w);
    float iw = fmaxf(ix2 - ix1, 0.0f), ih = fmaxf(iy2 - iy1, 0.0f);
    float inter = iw * ih;
    float parea = (p.z - p.x) * (p.w - p.y);
    return inter / (garea + parea - inter + EPSV);
}

// ---------------- K1: per (b,j) candidates + exact top-13 -> dense lists ------
__global__ __launch_bounds__(128) void k_topk(
    const float* __restrict__ ps,    // pred_scores [b,a,c]
    const float* __restrict__ pb,    // pred_bboxes [b,a,4]
    const float* __restrict__ ap,    // anchor_points [a,2]
    const int*   __restrict__ glab,  // gt_labels [b,j]
    const float* __restrict__ gbb,   // gt_bboxes [b,j,4]
    const float* __restrict__ mgt)   // mask_gt [b,j]
{
    __shared__ unsigned long long s_cand[CAND_CAP];
    __shared__ float s_iou[CAND_CAP];
    __shared__ int s_n;

    const int j = blockIdx.x, b = blockIdx.y;
    const int t = b * NJ + j;
    const int tid = threadIdx.x;

    if (tid < KTOP) g_topa[t * KTOP + tid] = -1;   // default: unused
    if (mgt[b * NJ + j] <= 0.0f) return;
    if (tid == 0) s_n = 0;

    const float4 gb4 = ((const float4*)gbb)[b * NJ + j];
    const float gx1 = gb4.x, gy1 = gb4.y, gx2 = gb4.z, gy2 = gb4.w;
    const float garea = (gx2 - gx1) * (gy2 - gy1);
    const int   lab = glab[b * NJ + j];
    __syncthreads();

    for (int a = tid; a < NA; a += 128) {
        float2 apt = ((const float2*)ap)[a];
        float m = fminf(fminf(apt.x - gx1, apt.y - gy1),
                        fminf(gx2 - apt.x, gy2 - apt.y));
        if (m > EPSV) {
            float4 p = ((const float4*)pb)[(size_t)b * NA + a];
            float iou = iou_box(gx1, gy1, gx2, gy2, p, garea);
            float sc = ps[((size_t)b * NA + a) * NC + lab];
            float i2 = iou * iou;
            float al = sc * (i2 * i2 * i2);          // score * iou^6
            int slot = atomicAdd(&s_n, 1);
            if (slot < CAND_CAP) {
                s_cand[slot] = ((unsigned long long)__float_as_uint(al) << 32)
                             | (unsigned)(~a);
                s_iou[slot] = iou;
            }
        }
    }
    __syncthreads();

    if (tid < 32) {                                   // warp 0: 13 max rounds
        int n = min(s_n, CAND_CAP);
        for (int it = 0; it < KTOP && it < n; ++it) {
            unsigned long long bv = 0ULL; int bs = -1;
            for (int c = tid; c < n; c += 32) {
                unsigned long long v = s_cand[c];
                if (v > bv) { bv = v; bs = c; }
            }
            #pragma unroll
            for (int off = 16; off; off >>= 1) {
                unsigned long long ov = __shfl_xor_sync(0xFFFFFFFFu, bv, off);
                int os = __shfl_xor_sync(0xFFFFFFFFu, bs, off);
                if (ov > bv) { bv = ov; bs = os; }
            }
            if ((unsigned)(bv >> 32) == 0u) break;    // only zero metrics remain
            if (tid == 0) {
                g_topa [t * KTOP + it] = (int)(~(unsigned)bv);
                g_topal[t * KTOP + it] = __uint_as_float((unsigned)(bv >> 32));
                g_topio[t * KTOP + it] = s_iou[bs];
                s_cand[bs] = 0ULL;
            }
            __syncwarp();
        }
    }
}

// ---------------- K2: per-batch resolution (one block per b) ------------------
__global__ __launch_bounds__(1024, 1) void k_resolve(
    const float* __restrict__ ps,
    const float* __restrict__ pb,
    const int*   __restrict__ glab,
    const float* __restrict__ gbb)
{
    __shared__ unsigned int  scnt[NA / 4];   // byte-packed claim counts
    __shared__ unsigned char ssgt[NA];       // assigned gt per claimed anchor
    __shared__ unsigned int  spal[NJ];       // pos_align bits (atomicMax)
    __shared__ unsigned int  spovl[NJ];      // pos_overlap bits

    const int b = blockIdx.x;
    const int tid = threadIdx.x;
    const int lane = tid & 31;

    for (int i = tid; i < NA / 4; i += 1024) scnt[i] = 0u;
    if (tid < NJ) { spal[tid] = 0u; spovl[tid] = 0u; }
    __syncthreads();

    // pass 1: claim counts
    for (int c = tid; c < NCLAIM; c += 1024) {
        int a = g_topa[b * NCLAIM + c];
        if (a >= 0) atomicAdd(&scnt[a >> 2], 1u << (8 * (a & 3)));
    }
    __syncthreads();

    // pass 2: resolve claims (solo inline, multi via warp-cooperative argmax)
    const int iters = (NCLAIM + 1023) / 1024;   // 2, uniform across warps
    for (int k = 0; k < iters; ++k) {
        int c = tid + k * 1024;
        bool act = c < NCLAIM;
        int a = -1, cnt = 0;
        if (act) {
            a = g_topa[b * NCLAIM + c];
            if (a >= 0) cnt = (scnt[a >> 2] >> (8 * (a & 3))) & 0xFF;
        }
        if (a >= 0 && cnt == 1) {
            int j = c / KTOP;
            float al  = g_topal[b * NCLAIM + c];
            float iou = g_topio[b * NCLAIM + c];
            ssgt[a] = (unsigned char)j;
            g_alsel[b * NA + a] = al;
            atomicMax(&spal[j],  __float_as_uint(al));
            atomicMax(&spovl[j], __float_as_uint(iou));
        }
        unsigned mm = __ballot_sync(0xFFFFFFFFu, a >= 0 && cnt > 1);
        while (mm) {
            int l = __ffs(mm) - 1; mm &= mm - 1;
            int aa = __shfl_sync(0xFFFFFFFFu, a, l);
            float4 p = ((const float4*)pb)[(size_t)b * NA + aa];
            unsigned long long bv = 0ULL;
            for (int j = lane; j < NJ; j += 32) {
                float4 g4 = ((const float4*)gbb)[b * NJ + j];
                float v = iou_box(g4.x, g4.y, g4.z, g4.w, p,
                                  (g4.z - g4.x) * (g4.w - g4.y));
                bv = max(bv, ((unsigned long long)__float_as_uint(v) << 32)
                             | (unsigned)(~j));
            }
            #pragma unroll
            for (int off = 16; off; off >>= 1)
                bv = max(bv, __shfl_xor_sync(0xFFFFFFFFu, bv, off));
            if (lane == 0) {     // duplicates write identical values: benign
                int g = (int)(~(unsigned)bv);
                float iou = __uint_as_float((unsigned)(bv >> 32));
                int lg = glab[b * NJ + g];
                float sc = ps[((size_t)b * NA + aa) * NC + lg];
                float i2 = iou * iou;
                float al = sc * (i2 * i2 * i2);
                ssgt[aa] = (unsigned char)g;
                g_alsel[b * NA + aa] = al;
                atomicMax(&spal[g],  __float_as_uint(al));
                atomicMax(&spovl[g], __float_as_uint(iou));
            }
        }
    }
    __syncthreads();

    // pass 3: emit per-anchor record + norm
    for (int a = tid; a < NA; a += 1024) {
        int cnt = (scnt[a >> 2] >> (8 * (a & 3))) & 0xFF;
        bool pos = cnt > 0;
        int g = pos ? (int)ssgt[a] : 0;
        float norm = 0.0f; int lab = NC;
        if (pos) {
            float pa = __uint_as_float(spal[g]);
            float po = __uint_as_float(spovl[g]);
            norm = g_alsel[b * NA + a] * po / (pa + EPSV);
            lab = glab[b * NJ + g];
        }
        g_rec [b * NA + a] = ((unsigned)lab << 16) | ((unsigned)g << 8) | (pos ? 1u : 0u);
        g_norm[b * NA + a] = norm;
    }
}

// ---------------- K3: streaming finalization (coalesced) ----------------------
#define NSC (BATCH * NA * (NC / 4))          // score float4 quads: 5,376,000
#define NTOT (NSC + BATCH * NA)              // + meta records

__global__ __launch_bounds__(256) void k_final(
    const float* __restrict__ gbb,
    float* __restrict__ out)
{
    int idx = blockIdx.x * blockDim.x + threadIdx.x;
    if (idx < NSC) {
        int i = idx / (NC / 4);
        int q = idx - i * (NC / 4);
        unsigned rec = g_rec[i];
        int lab = rec >> 16;
        float4 v = make_float4(0.f, 0.f, 0.f, 0.f);
        if ((lab >> 2) == q) ((float*)&v)[lab & 3] = g_norm[i];  // lab==NC: q=20 never
        ((float4*)(out + (size_t)BATCH * NA * 5))[idx] = v;
    } else if (idx < NTOT) {
        int i = idx - NSC;
        unsigned rec = g_rec[i];
        int lab = rec >> 16;
        int g = (rec >> 8) & 0xFF;
        bool pos = rec & 1u;
        int b = i / NA;
        out[i] = (float)lab;
        ((float4*)(out + BATCH * NA))[i] = ((const float4*)gbb)[b * NJ + g];
        out[(size_t)BATCH * NA * 85 + i] = pos ? 1.0f : 0.0f;
    }
}

// ---------------- launch ----------------
extern "C" void kernel_launch(void* const* d_in, const int* in_sizes, int n_in,
                              void* d_out, int out_size) {
    const float* pred_scores  = (const float*)d_in[0];
    const float* pred_bboxes  = (const float*)d_in[1];
    const float* anchor_pts   = (const float*)d_in[2];
    const int*   gt_labels    = (const int*)d_in[3];
    const float* gt_bboxes    = (const float*)d_in[4];
    const float* mask_gt      = (const float*)d_in[5];
    float* out = (float*)d_out;

    k_topk<<<dim3(NJ, BATCH), 128>>>(pred_scores, pred_bboxes, anchor_pts,
                                     gt_labels, gt_bboxes, mask_gt);

    k_resolve<<<BATCH, 1024>>>(pred_scores, pred_bboxes, gt_labels, gt_bboxes);

    k_final<<<(NTOT + 255) / 256, 256>>>(gt_bboxes, out);
}

// round 9
// speedup vs baseline: 1.2771x; 1.2771x over previous
#include <cuda_runtime.h>
#include <cuda_bf16.h>
#include <cstdint>

#define BATCH 32
#define NA 8400
#define NJ 100
#define NC 80
#define KTOP 13
#define EPSV 1e-9f
#define CAND_CAP 512
#define NCLAIM (NJ * KTOP)      // 1300 claims per image
#define NBY 32                  // y-bins of 20px over [0,640)
#define INVBW (32.0f / 640.0f)

// ---------------- device scratch (fully overwritten each call; no init) -------
__device__ int          g_topa [BATCH * NCLAIM];   // -1 = unused slot
__device__ float        g_topal[BATCH * NCLAIM];
__device__ float        g_topio[BATCH * NCLAIM];
__device__ float        g_alsel[BATCH * NA];       // read only where claimed
__device__ unsigned int g_rec  [BATCH * NA];       // (lab<<16)|(g<<8)|pos
__device__ float        g_norm [BATCH * NA];
__device__ int          g_binoff[NBY + 1];
__device__ int          g_bin_a[NA];
__device__ float2       g_bin_xy[NA];

__device__ __forceinline__ float iou_box(float gx1, float gy1, float gx2, float gy2,
                                         float4 p, float garea) {
    float ix1 = fmaxf(gx1, p.x), iy1 = fmaxf(gy1, p.y);
    float ix2 = fminf(gx2, p.z), iy2 = fminf(gy2, p.w);
    float iw = fmaxf(ix2 - ix1, 0.0f), ih = fmaxf(iy2 - iy1, 0.0f);
    float inter = iw * ih;
    float parea = (p.z - p.x) * (p.w - p.y);
    return inter / (garea + parea - inter + EPSV);
}

__device__ __forceinline__ int ybin(float y) {
    int v = (int)(y * INVBW);
    return max(0, min(NBY - 1, v));
}

// ---------------- K0: one-block y-bin prep (count -> scan -> scatter) ---------
__global__ __launch_bounds__(1024) void k_binprep(const float* __restrict__ ap) {
    __shared__ int scnt[NBY];
    __shared__ int scur[NBY];
    int tid = threadIdx.x;
    if (tid < NBY) scnt[tid] = 0;
    __syncthreads();
    for (int a = tid; a < NA; a += 1024) {
        float2 apt = ((const float2*)ap)[a];
        atomicAdd(&scnt[ybin(apt.y)], 1);
    }
    __syncthreads();
    if (tid < NBY) {
        int v = scnt[tid];
        int incl = v;
        #pragma unroll
        for (int off = 1; off < NBY; off <<= 1) {
            int o = __shfl_up_sync(0xFFFFFFFFu, incl, off);
            if (tid >= off) incl += o;
        }
        g_binoff[tid + 1] = incl;
        if (tid == 0) g_binoff[0] = 0;
        scur[tid] = incl - v;
    }
    __syncthreads();
    for (int a = tid; a < NA; a += 1024) {
        float2 apt = ((const float2*)ap)[a];
        int pos = atomicAdd(&scur[ybin(apt.y)], 1);
        g_bin_a[pos] = a;
        g_bin_xy[pos] = apt;
    }
}

// ---------------- K1: per (b,j) binned candidates + exact top-13 --------------
__global__ __launch_bounds__(256) void k_topk(
    const float* __restrict__ ps,    // pred_scores [b,a,c]
    const float* __restrict__ pb,    // pred_bboxes [b,a,4]
    const int*   __restrict__ glab,  // gt_labels [b,j]
    const float* __restrict__ gbb,   // gt_bboxes [b,j,4]
    const float* __restrict__ mgt)   // mask_gt [b,j]
{
    __shared__ unsigned long long s_cand[CAND_CAP];
    __shared__ float s_iou[CAND_CAP];
    __shared__ int s_n;

    const int j = blockIdx.x, b = blockIdx.y;
    const int t = b * NJ + j;
    const int tid = threadIdx.x;

    if (tid < KTOP) g_topa[t * KTOP + tid] = -1;       // default: unused
    if (mgt[t] <= 0.0f) return;
    if (tid == 0) s_n = 0;

    const float4 gb4 = ((const float4*)gbb)[t];
    const float gx1 = gb4.x, gy1 = gb4.y, gx2 = gb4.z, gy2 = gb4.w;
    const float garea = (gx2 - gx1) * (gy2 - gy1);
    const int   lab = glab[t];
    __syncthreads();

    const int cs = g_binoff[ybin(gy1)];
    const int ce = g_binoff[ybin(gy2) + 1];
    for (int c = cs + tid; c < ce; c += 256) {
        float2 apt = g_bin_xy[c];
        float m = fminf(fminf(apt.x - gx1, apt.y - gy1),
                        fminf(gx2 - apt.x, gy2 - apt.y));
        if (m > EPSV) {
            int a = g_bin_a[c];
            float4 p = ((const float4*)pb)[(size_t)b * NA + a];
            float iou = iou_box(gx1, gy1, gx2, gy2, p, garea);
            float sc = ps[((size_t)b * NA + a) * NC + lab];
            float i2 = iou * iou;
            float al = sc * (i2 * i2 * i2);            // score * iou^6
            int slot = atomicAdd(&s_n, 1);
            if (slot < CAND_CAP) {
                s_cand[slot] = ((unsigned long long)__float_as_uint(al) << 32)
                             | (unsigned)(~a);
                s_iou[slot] = iou;
            }
        }
    }
    __syncthreads();

    if (tid < 32) {                                    // warp 0: 13 max rounds
        int n = min(s_n, CAND_CAP);
        for (int it = 0; it < KTOP && it < n; ++it) {
            unsigned long long bv = 0ULL; int bs = -1;
            for (int c = tid; c < n; c += 32) {
                unsigned long long v = s_cand[c];
                if (v > bv) { bv = v; bs = c; }
            }
            #pragma unroll
            for (int off = 16; off; off >>= 1) {
                unsigned long long ov = __shfl_xor_sync(0xFFFFFFFFu, bv, off);
                int os = __shfl_xor_sync(0xFFFFFFFFu, bs, off);
                if (ov > bv) { bv = ov; bs = os; }
            }
            if ((unsigned)(bv >> 32) == 0u) break;     // only zero metrics remain
            if (tid == 0) {
                g_topa [t * KTOP + it] = (int)(~(unsigned)bv);
                g_topal[t * KTOP + it] = __uint_as_float((unsigned)(bv >> 32));
                g_topio[t * KTOP + it] = s_iou[bs];
                s_cand[bs] = 0ULL;
            }
            __syncwarp();
        }
    }
}

// ---------------- K2: per-batch resolution (one block per b) ------------------
__global__ __launch_bounds__(1024, 1) void k_resolve(
    const float* __restrict__ ps,
    const float* __restrict__ pb,
    const int*   __restrict__ glab,
    const float* __restrict__ gbb)
{
    __shared__ unsigned int  scnt[NA / 4];   // byte-packed claim counts
    __shared__ unsigned char ssgt[NA];       // assigned gt per claimed anchor
    __shared__ unsigned int  spal[NJ];       // pos_align bits (atomicMax)
    __shared__ unsigned int  spovl[NJ];      // pos_overlap bits

    const int b = blockIdx.x;
    const int tid = threadIdx.x;
    const int lane = tid & 31;

    for (int i = tid; i < NA / 4; i += 1024) scnt[i] = 0u;
    if (tid < NJ) { spal[tid] = 0u; spovl[tid] = 0u; }
    __syncthreads();

    // pass 1: claim counts
    for (int c = tid; c < NCLAIM; c += 1024) {
        int a = g_topa[b * NCLAIM + c];
        if (a >= 0) atomicAdd(&scnt[a >> 2], 1u << (8 * (a & 3)));
    }
    __syncthreads();

    // pass 2: resolve claims (solo inline, multi via warp-cooperative argmax)
    const int iters = (NCLAIM + 1023) / 1024;   // 2
    for (int k = 0; k < iters; ++k) {
        int c = tid + k * 1024;
        bool act = c < NCLAIM;
        int a = -1, cnt = 0;
        if (act) {
            a = g_topa[b * NCLAIM + c];
            if (a >= 0) cnt = (scnt[a >> 2] >> (8 * (a & 3))) & 0xFF;
        }
        if (a >= 0 && cnt == 1) {
            int j = c / KTOP;
            float al  = g_topal[b * NCLAIM + c];
            float iou = g_topio[b * NCLAIM + c];
            ssgt[a] = (unsigned char)j;
            g_alsel[b * NA + a] = al;
            atomicMax(&spal[j],  __float_as_uint(al));
            atomicMax(&spovl[j], __float_as_uint(iou));
        }
        unsigned mm = __ballot_sync(0xFFFFFFFFu, a >= 0 && cnt > 1);
        while (mm) {
            int l = __ffs(mm) - 1; mm &= mm - 1;
            int aa = __shfl_sync(0xFFFFFFFFu, a, l);
            float4 p = ((const float4*)pb)[(size_t)b * NA + aa];
            unsigned long long bv = 0ULL;
            for (int j = lane; j < NJ; j += 32) {
                float4 g4 = ((const float4*)gbb)[b * NJ + j];
                float v = iou_box(g4.x, g4.y, g4.z, g4.w, p,
                                  (g4.z - g4.x) * (g4.w - g4.y));
                bv = max(bv, ((unsigned long long)__float_as_uint(v) << 32)
                             | (unsigned)(~j));
            }
            #pragma unroll
            for (int off = 16; off; off >>= 1)
                bv = max(bv, __shfl_xor_sync(0xFFFFFFFFu, bv, off));
            if (lane == 0) {     // duplicates write identical values: benign
                int g = (int)(~(unsigned)bv);
                float iou = __uint_as_float((unsigned)(bv >> 32));
                int lg = glab[b * NJ + g];
                float sc = ps[((size_t)b * NA + aa) * NC + lg];
                float i2 = iou * iou;
                float al = sc * (i2 * i2 * i2);
                ssgt[aa] = (unsigned char)g;
                g_alsel[b * NA + aa] = al;
                atomicMax(&spal[g],  __float_as_uint(al));
                atomicMax(&spovl[g], __float_as_uint(iou));
            }
        }
    }
    __syncthreads();

    // pass 3: emit per-anchor record + norm
    for (int a = tid; a < NA; a += 1024) {
        int cnt = (scnt[a >> 2] >> (8 * (a & 3))) & 0xFF;
        bool pos = cnt > 0;
        int g = pos ? (int)ssgt[a] : 0;
        float norm = 0.0f; int lab = NC;
        if (pos) {
            float pa = __uint_as_float(spal[g]);
            float po = __uint_as_float(spovl[g]);
            norm = g_alsel[b * NA + a] * po / (pa + EPSV);
            lab = glab[b * NJ + g];
        }
        g_rec [b * NA + a] = ((unsigned)lab << 16) | ((unsigned)g << 8) | (pos ? 1u : 0u);
        g_norm[b * NA + a] = norm;
    }
}

// ---------------- K3: streaming finalization (coalesced) ----------------------
#define NSC (BATCH * NA * (NC / 4))          // score float4 quads: 5,376,000
#define NTOT (NSC + BATCH * NA)

__global__ __launch_bounds__(256) void k_final(
    const float* __restrict__ gbb,
    float* __restrict__ out)
{
    int idx = blockIdx.x * blockDim.x + threadIdx.x;
    if (idx < NSC) {
        int i = idx / (NC / 4);
        int q = idx - i * (NC / 4);
        unsigned rec = g_rec[i];
        int lab = rec >> 16;
        float4 v = make_float4(0.f, 0.f, 0.f, 0.f);
        if ((lab >> 2) == q) ((float*)&v)[lab & 3] = g_norm[i];  // lab==NC never hits
        ((float4*)(out + (size_t)BATCH * NA * 5))[idx] = v;
    } else if (idx < NTOT) {
        int i = idx - NSC;
        unsigned rec = g_rec[i];
        int lab = rec >> 16;
        int g = (rec >> 8) & 0xFF;
        bool pos = rec & 1u;
        int b = i / NA;
        out[i] = (float)lab;
        ((float4*)(out + BATCH * NA))[i] = ((const float4*)gbb)[b * NJ + g];
        out[(size_t)BATCH * NA * 85 + i] = pos ? 1.0f : 0.0f;
    }
}

// ---------------- launch ----------------
extern "C" void kernel_launch(void* const* d_in, const int* in_sizes, int n_in,
                              void* d_out, int out_size) {
    const float* pred_scores  = (const float*)d_in[0];
    const float* pred_bboxes  = (const float*)d_in[1];
    const float* anchor_pts   = (const float*)d_in[2];
    const int*   gt_labels    = (const int*)d_in[3];
    const float* gt_bboxes    = (const float*)d_in[4];
    const float* mask_gt      = (const float*)d_in[5];
    float* out = (float*)d_out;

    k_binprep<<<1, 1024>>>(anchor_pts);

    k_topk<<<dim3(NJ, BATCH), 256>>>(pred_scores, pred_bboxes,
                                     gt_labels, gt_bboxes, mask_gt);

    k_resolve<<<BATCH, 1024>>>(pred_scores, pred_bboxes, gt_labels, gt_bboxes);

    k_final<<<(NTOT + 255) / 256, 256>>>(gt_bboxes, out);
}

// round 10
// speedup vs baseline: 1.6011x; 1.2537x over previous
#include <cuda_runtime.h>
#include <cuda_bf16.h>
#include <cstdint>

#define BATCH 32
#define NA 8400
#define NJ 100
#define NC 80
#define KTOP 13
#define EPSV 1e-9f
#define CAND_CAP 512
#define NCLAIM (NJ * KTOP)      // 1300 claims per image
#define NBY 32                  // y-bins of 20px over [0,640)
#define INVBW (32.0f / 640.0f)

// ---------------- device scratch (fully overwritten each call; no init) -------
__device__ int          g_topa [BATCH * NCLAIM];   // -1 = unused slot
__device__ float        g_topal[BATCH * NCLAIM];
__device__ float        g_topio[BATCH * NCLAIM];
__device__ float        g_alsel[BATCH * NA];       // read only where claimed
__device__ unsigned int g_rec  [BATCH * NA];       // (lab<<16)|(g<<8)|pos
__device__ float        g_norm [BATCH * NA];
__device__ int          g_binoff[NBY + 1];
__device__ int          g_bin_a[NA];
__device__ float2       g_bin_xy[NA];

__device__ __forceinline__ float iou_box(float gx1, float gy1, float gx2, float gy2,
                                         float4 p, float garea) {
    float ix1 = fmaxf(gx1, p.x), iy1 = fmaxf(gy1, p.y);
    float ix2 = fminf(gx2, p.z), iy2 = fminf(gy2, p.w);
    float iw = fmaxf(ix2 - ix1, 0.0f), ih = fmaxf(iy2 - iy1, 0.0f);
    float inter = iw * ih;
    float parea = (p.z - p.x) * (p.w - p.y);
    return inter / (garea + parea - inter + EPSV);
}

__device__ __forceinline__ int ybin(float y) {
    int v = (int)(y * INVBW);
    return max(0, min(NBY - 1, v));
}

// ---------------- K0: one-block y-bin prep (count -> scan -> scatter) ---------
__global__ __launch_bounds__(1024) void k_binprep(const float* __restrict__ ap) {
    __shared__ int scnt[NBY];
    __shared__ int scur[NBY];
    int tid = threadIdx.x;
    if (tid < NBY) scnt[tid] = 0;
    __syncthreads();
    for (int a = tid; a < NA; a += 1024) {
        float2 apt = ((const float2*)ap)[a];
        atomicAdd(&scnt[ybin(apt.y)], 1);
    }
    __syncthreads();
    if (tid < NBY) {
        int v = scnt[tid];
        int incl = v;
        #pragma unroll
        for (int off = 1; off < NBY; off <<= 1) {
            int o = __shfl_up_sync(0xFFFFFFFFu, incl, off);
            if (tid >= off) incl += o;
        }
        g_binoff[tid + 1] = incl;
        if (tid == 0) g_binoff[0] = 0;
        scur[tid] = incl - v;
    }
    __syncthreads();
    for (int a = tid; a < NA; a += 1024) {
        float2 apt = ((const float2*)ap)[a];
        int pos = atomicAdd(&scur[ybin(apt.y)], 1);
        g_bin_a[pos] = a;
        g_bin_xy[pos] = apt;
    }
}

// ---------------- K1: per (b,j) binned candidates + exact top-13 --------------
__global__ __launch_bounds__(256) void k_topk(
    const float* __restrict__ ps,    // pred_scores [b,a,c]
    const float* __restrict__ pb,    // pred_bboxes [b,a,4]
    const int*   __restrict__ glab,  // gt_labels [b,j]
    const float* __restrict__ gbb,   // gt_bboxes [b,j,4]
    const float* __restrict__ mgt)   // mask_gt [b,j]
{
    __shared__ unsigned long long s_cand[CAND_CAP];
    __shared__ float s_iou[CAND_CAP];
    __shared__ int s_n;

    const int j = blockIdx.x, b = blockIdx.y;
    const int t = b * NJ + j;
    const int tid = threadIdx.x;
    const int lane = tid & 31;

    if (tid < KTOP) g_topa[t * KTOP + tid] = -1;       // default: unused
    if (mgt[t] <= 0.0f) return;
    if (tid == 0) s_n = 0;

    const float4 gb4 = ((const float4*)gbb)[t];
    const float gx1 = gb4.x, gy1 = gb4.y, gx2 = gb4.z, gy2 = gb4.w;
    const float garea = (gx2 - gx1) * (gy2 - gy1);
    const int   lab = glab[t];
    __syncthreads();

    const int cs = g_binoff[ybin(gy1)];
    const int ce = g_binoff[ybin(gy2) + 1];
    for (int c0 = cs; c0 < ce; c0 += 256) {
        int c = c0 + tid;
        bool act = c < ce;
        float2 apt = act ? g_bin_xy[c] : make_float2(-1e9f, -1e9f);
        float m = fminf(fminf(apt.x - gx1, apt.y - gy1),
                        fminf(gx2 - apt.x, gy2 - apt.y));
        bool take = act && m > EPSV;
        // warp-aggregated slot allocation
        unsigned bal = __ballot_sync(0xFFFFFFFFu, take);
        int ldr = __ffs(bal) - 1;
        int base = 0;
        if (bal) {
            if (lane == ldr) base = atomicAdd(&s_n, __popc(bal));
            base = __shfl_sync(0xFFFFFFFFu, base, ldr);
        }
        if (take) {
            int slot = base + __popc(bal & ((1u << lane) - 1u));
            int a = g_bin_a[c];
            float4 p = ((const float4*)pb)[(size_t)b * NA + a];
            float iou = iou_box(gx1, gy1, gx2, gy2, p, garea);
            float sc = ps[((size_t)b * NA + a) * NC + lab];
            float i2 = iou * iou;
            float al = sc * (i2 * i2 * i2);            // score * iou^6
            if (slot < CAND_CAP) {
                s_cand[slot] = ((unsigned long long)__float_as_uint(al) << 32)
                             | (unsigned)(~a);
                s_iou[slot] = iou;
            }
        }
    }
    __syncthreads();

    if (tid < 32) {                                    // warp 0: 13 max rounds
        int n = min(s_n, CAND_CAP);
        for (int it = 0; it < KTOP && it < n; ++it) {
            unsigned long long bv = 0ULL; int bs = -1;
            for (int c = tid; c < n; c += 32) {
                unsigned long long v = s_cand[c];
                if (v > bv) { bv = v; bs = c; }
            }
            #pragma unroll
            for (int off = 16; off; off >>= 1) {
                unsigned long long ov = __shfl_xor_sync(0xFFFFFFFFu, bv, off);
                int os = __shfl_xor_sync(0xFFFFFFFFu, bs, off);
                if (ov > bv) { bv = ov; bs = os; }
            }
            if ((unsigned)(bv >> 32) == 0u) break;     // only zero metrics remain
            if (tid == 0) {
                g_topa [t * KTOP + it] = (int)(~(unsigned)bv);
                g_topal[t * KTOP + it] = __uint_as_float((unsigned)(bv >> 32));
                g_topio[t * KTOP + it] = s_iou[bs];
                s_cand[bs] = 0ULL;
            }
            __syncwarp();
        }
    }
}

// ---------------- K2: per-batch resolution (one block per b) ------------------
__global__ __launch_bounds__(1024, 1) void k_resolve(
    const float* __restrict__ ps,
    const float* __restrict__ pb,
    const int*   __restrict__ glab,
    const float* __restrict__ gbb)
{
    __shared__ unsigned int  scnt[NA / 4];   // byte-packed claim counts
    __shared__ unsigned char ssgt[NA];       // assigned gt per claimed anchor
    __shared__ unsigned int  spal[NJ];       // pos_align bits (atomicMax)
    __shared__ unsigned int  spovl[NJ];      // pos_overlap bits
    __shared__ float4        sgbb[NJ];       // gt boxes (SMEM-resident argmax)
    __shared__ int           sglab[NJ];
    __shared__ int           smulti[NCLAIM]; // multi-claim anchor list (dupes ok)
    __shared__ int           snm;

    const int b = blockIdx.x;
    const int tid = threadIdx.x;
    const int lane = tid & 31;
    const int wid = tid >> 5;

    for (int i = tid; i < NA / 4; i += 1024) scnt[i] = 0u;
    if (tid < NJ) {
        spal[tid] = 0u; spovl[tid] = 0u;
        sgbb[tid]  = ((const float4*)gbb)[b * NJ + tid];
        sglab[tid] = glab[b * NJ + tid];
    }
    if (tid == 0) snm = 0;
    __syncthreads();

    // pass 1: claim counts
    for (int c = tid; c < NCLAIM; c += 1024) {
        int a = g_topa[b * NCLAIM + c];
        if (a >= 0) atomicAdd(&scnt[a >> 2], 1u << (8 * (a & 3)));
    }
    __syncthreads();

    // pass 2a: solo claims inline; multi claims -> shared list
    for (int c = tid; c < NCLAIM; c += 1024) {
        int a = g_topa[b * NCLAIM + c];
        if (a >= 0) {
            int cnt = (scnt[a >> 2] >> (8 * (a & 3))) & 0xFF;
            if (cnt == 1) {
                int j = c / KTOP;
                float al  = g_topal[b * NCLAIM + c];
                float iou = g_topio[b * NCLAIM + c];
                ssgt[a] = (unsigned char)j;
                g_alsel[b * NA + a] = al;
                atomicMax(&spal[j],  __float_as_uint(al));
                atomicMax(&spovl[j], __float_as_uint(iou));
            } else {
                smulti[atomicAdd(&snm, 1)] = a;   // duplicates are idempotent
            }
        }
    }
    __syncthreads();

    // pass 2b: ALL warps strip-mine the multi list; argmax over SMEM gt boxes
    const int nm = snm;
    for (int m = wid; m < nm; m += 32) {
        int aa = smulti[m];
        float4 p = ((const float4*)pb)[(size_t)b * NA + aa];
        unsigned long long bv = 0ULL;
        #pragma unroll 1
        for (int j = lane; j < NJ; j += 32) {
            float4 g4 = sgbb[j];
            float v = iou_box(g4.x, g4.y, g4.z, g4.w, p,
                              (g4.z - g4.x) * (g4.w - g4.y));
            bv = max(bv, ((unsigned long long)__float_as_uint(v) << 32)
                         | (unsigned)(~j));
        }
        #pragma unroll
        for (int off = 16; off; off >>= 1)
            bv = max(bv, __shfl_xor_sync(0xFFFFFFFFu, bv, off));
        if (lane == 0) {     // duplicate entries write identical values: benign
            int g = (int)(~(unsigned)bv);
            float iou = __uint_as_float((unsigned)(bv >> 32));
            int lg = sglab[g];
            float sc = ps[((size_t)b * NA + aa) * NC + lg];
            float i2 = iou * iou;
            float al = sc * (i2 * i2 * i2);
            ssgt[aa] = (unsigned char)g;
            g_alsel[b * NA + aa] = al;
            atomicMax(&spal[g],  __float_as_uint(al));
            atomicMax(&spovl[g], __float_as_uint(iou));
        }
    }
    __syncthreads();

    // pass 3: emit per-anchor record + norm
    for (int a = tid; a < NA; a += 1024) {
        int cnt = (scnt[a >> 2] >> (8 * (a & 3))) & 0xFF;
        bool pos = cnt > 0;
        int g = pos ? (int)ssgt[a] : 0;
        float norm = 0.0f; int lab = NC;
        if (pos) {
            float pa = __uint_as_float(spal[g]);
            float po = __uint_as_float(spovl[g]);
            norm = g_alsel[b * NA + a] * po / (pa + EPSV);
            lab = sglab[g];
        }
        g_rec [b * NA + a] = ((unsigned)lab << 16) | ((unsigned)g << 8) | (pos ? 1u : 0u);
        g_norm[b * NA + a] = norm;
    }
}

// ---------------- K3: streaming finalization (coalesced) ----------------------
#define NSC (BATCH * NA * (NC / 4))          // score float4 quads: 5,376,000
#define NTOT (NSC + BATCH * NA)

__global__ __launch_bounds__(256) void k_final(
    const float* __restrict__ gbb,
    float* __restrict__ out)
{
    int idx = blockIdx.x * blockDim.x + threadIdx.x;
    if (idx < NSC) {
        int i = idx / (NC / 4);
        int q = idx - i * (NC / 4);
        unsigned rec = g_rec[i];
        int lab = rec >> 16;
        float4 v = make_float4(0.f, 0.f, 0.f, 0.f);
        if ((lab >> 2) == q) ((float*)&v)[lab & 3] = g_norm[i];  // lab==NC never hits
        ((float4*)(out + (size_t)BATCH * NA * 5))[idx] = v;
    } else if (idx < NTOT) {
        int i = idx - NSC;
        unsigned rec = g_rec[i];
        int lab = rec >> 16;
        int g = (rec >> 8) & 0xFF;
        bool pos = rec & 1u;
        int b = i / NA;
        out[i] = (float)lab;
        ((float4*)(out + BATCH * NA))[i] = ((const float4*)gbb)[b * NJ + g];
        out[(size_t)BATCH * NA * 85 + i] = pos ? 1.0f : 0.0f;
    }
}

// ---------------- launch ----------------
extern "C" void kernel_launch(void* const* d_in, const int* in_sizes, int n_in,
                              void* d_out, int out_size) {
    const float* pred_scores  = (const float*)d_in[0];
    const float* pred_bboxes  = (const float*)d_in[1];
    const float* anchor_pts   = (const float*)d_in[2];
    const int*   gt_labels    = (const int*)d_in[3];
    const float* gt_bboxes    = (const float*)d_in[4];
    const float* mask_gt      = (const float*)d_in[5];
    float* out = (float*)d_out;

    k_binprep<<<1, 1024>>>(anchor_pts);

    k_topk<<<dim3(NJ, BATCH), 256>>>(pred_scores, pred_bboxes,
                                     gt_labels, gt_bboxes, mask_gt);

    k_resolve<<<BATCH, 1024>>>(pred_scores, pred_bboxes, gt_labels, gt_bboxes);

    k_final<<<(NTOT + 255) / 256, 256>>>(gt_bboxes, out);
}